// round 7
// baseline (speedup 1.0000x reference)
#include <cuda_runtime.h>

// Inputs (metadata order):
// 0: user_id  int32 [16384]
// 1: item_id  int32 [16384]
// 2: category int32 [16384]
// 3: emb_user f32   [100000]
// 4: emb_item f32   [50000]
// 5: emb_cat  f32   [1000]
// 6: cross_w  f32   [150000000]
// out: f32 [16384]

#define D_USER  100000
#define D_ITEM  50000
#define D_CAT   1000
#define OFF_IC  (D_USER * D_CAT)   // 100,000,000

// 4 rows per thread: 4096 threads = 32 CTAs x 128.
__global__ __launch_bounds__(128, 1)
void wide_kernel4(const int4* __restrict__ user_id,
                  const int4* __restrict__ item_id,
                  const int4* __restrict__ category,
                  const float* __restrict__ emb_user,
                  const float* __restrict__ emb_item,
                  const float* __restrict__ emb_cat,
                  const float* __restrict__ cross_w,
                  float4* __restrict__ out,
                  int n4)
{
    int t = blockIdx.x * 128 + threadIdx.x;
    if (t >= n4) return;

    // Three coalesced 16B index loads (independent).
    int4 u4 = __ldg(&user_id[t]);
    int4 i4 = __ldg(&item_id[t]);
    int4 c4 = __ldg(&category[t]);

    // 8 independent long-latency gathers into the 600MB table, issued first.
    float uc0 = __ldg(&cross_w[u4.x * D_CAT + c4.x]);
    float uc1 = __ldg(&cross_w[u4.y * D_CAT + c4.y]);
    float uc2 = __ldg(&cross_w[u4.z * D_CAT + c4.z]);
    float uc3 = __ldg(&cross_w[u4.w * D_CAT + c4.w]);
    float ic0 = __ldg(&cross_w[OFF_IC + i4.x * D_CAT + c4.x]);
    float ic1 = __ldg(&cross_w[OFF_IC + i4.y * D_CAT + c4.y]);
    float ic2 = __ldg(&cross_w[OFF_IC + i4.z * D_CAT + c4.z]);
    float ic3 = __ldg(&cross_w[OFF_IC + i4.w * D_CAT + c4.w]);

    // 12 small-table gathers (L2-resident).
    float eu0 = __ldg(&emb_user[u4.x]), eu1 = __ldg(&emb_user[u4.y]);
    float eu2 = __ldg(&emb_user[u4.z]), eu3 = __ldg(&emb_user[u4.w]);
    float ei0 = __ldg(&emb_item[i4.x]), ei1 = __ldg(&emb_item[i4.y]);
    float ei2 = __ldg(&emb_item[i4.z]), ei3 = __ldg(&emb_item[i4.w]);
    float ec0 = __ldg(&emb_cat[c4.x]),  ec1 = __ldg(&emb_cat[c4.y]);
    float ec2 = __ldg(&emb_cat[c4.z]),  ec3 = __ldg(&emb_cat[c4.w]);

    float4 r;
    r.x = ((eu0 + ei0) + (ec0 + uc0)) + ic0;
    r.y = ((eu1 + ei1) + (ec1 + uc1)) + ic1;
    r.z = ((eu2 + ei2) + (ec2 + uc2)) + ic2;
    r.w = ((eu3 + ei3) + (ec3 + uc3)) + ic3;
    out[t] = r;
}

extern "C" void kernel_launch(void* const* d_in, const int* in_sizes, int n_in,
                              void* d_out, int out_size)
{
    const int4*  user_id  = (const int4*)d_in[0];
    const int4*  item_id  = (const int4*)d_in[1];
    const int4*  category = (const int4*)d_in[2];
    const float* emb_user = (const float*)d_in[3];
    const float* emb_item = (const float*)d_in[4];
    const float* emb_cat  = (const float*)d_in[5];
    const float* cross_w  = (const float*)d_in[6];
    float4* out = (float4*)d_out;

    int n  = in_sizes[0];      // 16384
    int n4 = n / 4;            // 4096 threads, exact
    int threads = 128;
    int blocks = (n4 + threads - 1) / threads;  // 32 CTAs
    wide_kernel4<<<blocks, threads>>>(user_id, item_id, category,
                                      emb_user, emb_item, emb_cat, cross_w,
                                      out, n4);
}

// round 10
// speedup vs baseline: 1.0093x; 1.0093x over previous
#include <cuda_runtime.h>

// Inputs (metadata order):
// 0: user_id  int32 [16384]
// 1: item_id  int32 [16384]
// 2: category int32 [16384]
// 3: emb_user f32   [100000]
// 4: emb_item f32   [50000]
// 5: emb_cat  f32   [1000]
// 6: cross_w  f32   [150000000]
// out: f32 [16384]
//
// Latency-bound gather kernel at the launch-overhead floor (~6.7us =
// T_ovh ~5000cyc + one L2->DRAM dependent-load chain + replay dispatch).
// Measured: 64x256 scalar = 6.656us; 128x128 scalar = 6.912; 32x128 x4-vec
// = 6.912. Grid shape and instruction count are not levers; keep the best.

#define D_USER  100000
#define D_ITEM  50000
#define D_CAT   1000
#define OFF_IC  (D_USER * D_CAT)   // 100,000,000

__global__ __launch_bounds__(256, 1)
void wide_kernel(const int* __restrict__ user_id,
                 const int* __restrict__ item_id,
                 const int* __restrict__ category,
                 const float* __restrict__ emb_user,
                 const float* __restrict__ emb_item,
                 const float* __restrict__ emb_cat,
                 const float* __restrict__ cross_w,
                 float* __restrict__ out,
                 int n)
{
    int i = blockIdx.x * 256 + threadIdx.x;
    if (i >= n) return;

    // Three coalesced index loads (independent).
    int u  = __ldg(&user_id[i]);
    int it = __ldg(&item_id[i]);
    int c  = __ldg(&category[i]);

    // Two long-latency random gathers into the 600MB table issued first,
    // then the three small-table lookups. All five independent -> MLP=5.
    float cw0 = __ldg(&cross_w[u * D_CAT + c]);
    float cw1 = __ldg(&cross_w[OFF_IC + it * D_CAT + c]);
    float eu  = __ldg(&emb_user[u]);
    float ei  = __ldg(&emb_item[it]);
    float ec  = __ldg(&emb_cat[c]);

    out[i] = ((eu + ei) + (ec + cw0)) + cw1;
}

extern "C" void kernel_launch(void* const* d_in, const int* in_sizes, int n_in,
                              void* d_out, int out_size)
{
    const int*   user_id  = (const int*)d_in[0];
    const int*   item_id  = (const int*)d_in[1];
    const int*   category = (const int*)d_in[2];
    const float* emb_user = (const float*)d_in[3];
    const float* emb_item = (const float*)d_in[4];
    const float* emb_cat  = (const float*)d_in[5];
    const float* cross_w  = (const float*)d_in[6];
    float* out = (float*)d_out;

    int n = in_sizes[0];  // 16384
    int threads = 256;
    int blocks = (n + threads - 1) / threads;  // 64 CTAs
    wide_kernel<<<blocks, threads>>>(user_id, item_id, category,
                                     emb_user, emb_item, emb_cat, cross_w,
                                     out, n);
}